// round 4
// baseline (speedup 1.0000x reference)
#include <cuda_runtime.h>
#include <cstdint>

#define N_NODES 1000000
#define N_ELEMS 4000000

// ---------------- scratch (device globals; no allocs allowed) ----------------
// Per-node accumulators, stride 4 (16B aligned) so scatter can use
// red.global.add.v4.f32 and the node pass uses float4 loads.
__device__ __align__(16) float g_F[N_NODES * 4];   // F_int
__device__ __align__(16) float g_M[N_NODES * 4];   // M_int
__device__ __align__(16) float g_X[N_NODES * 4];   // F_ext

// Scalar accumulators (doubles; counts fit exactly).
// 0: sum_rkin  1: L_sum  2: S_fext  3: S_fr  4: S_mr_free  5: S_mr_pin
// 6: n_fd  7: n_fr  8: n_pin
__device__ double g_sc[9];
__device__ unsigned int g_qmax_bits;  // max |elem_load| (nonneg float as uint)
__device__ unsigned int g_lmax_bits;  // max L
__device__ int g_conn_is64;           // 1 if conn stored as int64 pairs

// ---------------- reduction helpers ----------------
__device__ __forceinline__ double warpSumD(double v) {
    #pragma unroll
    for (int o = 16; o > 0; o >>= 1) v += __shfl_down_sync(0xffffffffu, v, o);
    return v;
}
__device__ __forceinline__ float warpMaxF(float v) {
    #pragma unroll
    for (int o = 16; o > 0; o >>= 1) v = fmaxf(v, __shfl_down_sync(0xffffffffu, v, o));
    return v;
}

__device__ __forceinline__ void redAddV4(float* p, float a, float b, float c, float d) {
    asm volatile("red.global.add.v4.f32 [%0], {%1, %2, %3, %4};"
                 :: "l"(p), "f"(a), "f"(b), "f"(c), "f"(d) : "memory");
}

// ---------------- conn dtype detection ----------------
// int64 layout: words are [i_lo, i_hi, j_lo, j_hi, ...] with hi words == 0
// (node ids < 2^20). int32 layout: words are [i, j, i, j, ...]; odd words are
// j-indices, essentially never all zero across 64 samples.
__global__ void detect_conn_kernel(const unsigned int* __restrict__ conn_w)
{
    if (threadIdx.x == 0) {
        int all_odd_zero = 1;
        #pragma unroll 8
        for (int k = 0; k < 64; ++k) {
            if (conn_w[2 * k + 1] != 0u) { all_odd_zero = 0; break; }
        }
        g_conn_is64 = all_odd_zero;
    }
}

// ---------------- element pass ----------------
__global__ __launch_bounds__(256)
void elem_kernel(const float* __restrict__ phi,
                 const float* __restrict__ gux,
                 const float* __restrict__ guz,
                 const float* __restrict__ gphi,
                 const float* __restrict__ pE,
                 const float* __restrict__ pA,
                 const float* __restrict__ pI,
                 const float* __restrict__ Lq,
                 const float* __restrict__ dirs,
                 const float* __restrict__ loads,
                 const int*   __restrict__ conn)
{
    const int is64 = g_conn_is64;

    double t_rkin = 0.0, t_Lsum = 0.0;
    float t_qmax = 0.0f, t_lmax = 0.0f;

    for (int e = blockIdx.x * blockDim.x + threadIdx.x; e < N_ELEMS;
         e += gridDim.x * blockDim.x) {
        float x0 = dirs[3 * e + 0];
        float x1 = dirs[3 * e + 1];
        float x2 = dirs[3 * e + 2];

        int i, j;
        if (is64) {
            i = conn[4 * (size_t)e + 0];   // low word of int64 i
            j = conn[4 * (size_t)e + 2];   // low word of int64 j
        } else {
            i = conn[2 * (size_t)e + 0];
            j = conn[2 * (size_t)e + 1];
        }

        float L  = Lq[e];
        float E  = pE[e];
        float EA = E * pA[e];
        float EI = E * pI[e];

        // local axes: z_hat = normalize(cross(x_hat, ref)), ref = |x1|>0.99 ? e3 : e2
        float zx, zy, zz;
        if (fabsf(x1) > 0.99f) { zx = x1;  zy = -x0; zz = 0.0f; }  // cross(x, e3)
        else                   { zx = -x2; zy = 0.0f; zz = x0;  }  // cross(x, e2)
        float zn = fmaxf(sqrtf(zx * zx + zy * zy + zz * zz), 1e-8f);
        float zinv = 1.0f / zn;
        zx *= zinv; zy *= zinv; zz *= zinv;
        // y_hat = normalize(cross(z_hat, x_hat))
        float yx = zy * x2 - zz * x1;
        float yy = zz * x0 - zx * x2;
        float yz = zx * x1 - zy * x0;
        float yn = fmaxf(sqrtf(yx * yx + yy * yy + yz * yz), 1e-8f);
        float yinv = 1.0f / yn;
        yx *= yinv; yy *= yinv; yz *= yinv;

        // gathers (node data is L2-resident)
        const float* gui = gux  + 3 * (size_t)i;  const float* guj = gux  + 3 * (size_t)j;
        const float* gzi = guz  + 3 * (size_t)i;  const float* gzj = guz  + 3 * (size_t)j;
        const float* gpi = gphi + 3 * (size_t)i;  const float* gpj = gphi + 3 * (size_t)j;
        float gux_i = gui[0] * x0 + gui[1] * x1 + gui[2] * x2;
        float gux_j = guj[0] * x0 + guj[1] * x1 + guj[2] * x2;
        float guz_i = gzi[0] * x0 + gzi[1] * x1 + gzi[2] * x2;
        float guz_j = gzj[0] * x0 + gzj[1] * x1 + gzj[2] * x2;
        float kap_i = gpi[0] * x0 + gpi[1] * x1 + gpi[2] * x2;
        float kap_j = gpj[0] * x0 + gpj[1] * x1 + gpj[2] * x2;

        float eps_i = x0 * gux_i + x2 * guz_i;
        float eps_j = x0 * gux_j + x2 * guz_j;
        float Navg  = 0.5f * EA * (eps_i + eps_j);
        float Mi = EI * kap_i;
        float Mj = EI * kap_j;
        float V  = (Mj - Mi) / L;

        float Fx = Navg * x0 + V * zx;
        float Fy = Navg * x1 + V * zy;
        float Fz = Navg * x2 + V * zz;

        float l0 = loads[3 * e + 0];
        float l1 = loads[3 * e + 1];
        float l2 = loads[3 * e + 2];
        float hl = 0.5f * L;

        // vectorized scatter-add: 6 x red.global.add.v4.f32 (pad lane adds 0)
        redAddV4(&g_F[4 * (size_t)i],  Fx,  Fy,  Fz, 0.0f);
        redAddV4(&g_F[4 * (size_t)j], -Fx, -Fy, -Fz, 0.0f);
        redAddV4(&g_M[4 * (size_t)i], Mi * yx, Mi * yy, Mi * yz, 0.0f);
        redAddV4(&g_M[4 * (size_t)j], Mj * yx, Mj * yy, Mj * yz, 0.0f);
        redAddV4(&g_X[4 * (size_t)i], l0 * hl, l1 * hl, l2 * hl, 0.0f);
        redAddV4(&g_X[4 * (size_t)j], l0 * hl, l1 * hl, l2 * hl, 0.0f);

        // kinematics
        float du_i = zx * gux_i + zz * guz_i;
        float du_j = zx * gux_j + zz * guz_j;
        float ri = phi[i] - du_i;
        float rj = phi[j] - du_j;
        t_rkin += (double)(ri * ri) + (double)(rj * rj);

        t_Lsum += (double)L;
        t_lmax  = fmaxf(t_lmax, L);
        t_qmax  = fmaxf(t_qmax, fmaxf(fabsf(l0), fmaxf(fabsf(l1), fabsf(l2))));
    }

    // warp-level reduction, one atomic per warp per quantity
    t_rkin = warpSumD(t_rkin);
    t_Lsum = warpSumD(t_Lsum);
    t_qmax = warpMaxF(t_qmax);
    t_lmax = warpMaxF(t_lmax);
    if ((threadIdx.x & 31) == 0) {
        atomicAdd(&g_sc[0], t_rkin);
        atomicAdd(&g_sc[1], t_Lsum);
        atomicMax(&g_qmax_bits, __float_as_uint(t_qmax));
        atomicMax(&g_lmax_bits, __float_as_uint(t_lmax));
    }
}

// ---------------- node pass ----------------
__global__ __launch_bounds__(256)
void node_kernel(const float* __restrict__ bc_disp,
                 const float* __restrict__ bc_rot)
{
    double t_sfext = 0.0, t_sfr = 0.0, t_smrf = 0.0, t_smrp = 0.0;
    double t_nfd = 0.0, t_nfr = 0.0, t_npin = 0.0;

    const float4* F4 = reinterpret_cast<const float4*>(g_F);
    const float4* M4 = reinterpret_cast<const float4*>(g_M);
    const float4* X4 = reinterpret_cast<const float4*>(g_X);

    for (int n = blockIdx.x * blockDim.x + threadIdx.x; n < N_NODES;
         n += gridDim.x * blockDim.x) {
        float bd = bc_disp[n];
        float br = bc_rot[n];
        bool fd  = bd < 0.5f;
        bool fr  = br < 0.5f;
        bool pin = (bd > 0.5f) && (br < 0.5f);

        float4 F = F4[n];
        float4 M = M4[n];
        float4 X = X4[n];

        float fex2 = X.x * X.x + X.y * X.y + X.z * X.z;
        float rx = F.x + X.x, ry = F.y + X.y, rz = F.z + X.z;
        float fr2  = rx * rx + ry * ry + rz * rz;
        float m2   = M.x * M.x + M.y * M.y + M.z * M.z;

        if (fd)  { t_nfd  += 1.0; t_sfext += (double)fex2; t_sfr += (double)fr2; }
        if (fr)  { t_nfr  += 1.0; t_smrf  += (double)m2; }
        if (pin) { t_npin += 1.0; t_smrp  += (double)m2; }
    }

    t_sfext = warpSumD(t_sfext);
    t_sfr   = warpSumD(t_sfr);
    t_smrf  = warpSumD(t_smrf);
    t_smrp  = warpSumD(t_smrp);
    t_nfd   = warpSumD(t_nfd);
    t_nfr   = warpSumD(t_nfr);
    t_npin  = warpSumD(t_npin);
    if ((threadIdx.x & 31) == 0) {
        atomicAdd(&g_sc[2], t_sfext);
        atomicAdd(&g_sc[3], t_sfr);
        atomicAdd(&g_sc[4], t_smrf);
        atomicAdd(&g_sc[5], t_smrp);
        atomicAdd(&g_sc[6], t_nfd);
        atomicAdd(&g_sc[7], t_nfr);
        atomicAdd(&g_sc[8], t_npin);
    }
}

// ---------------- finalize ----------------
__global__ void finalize_kernel(float* __restrict__ out)
{
    double sum_rkin = g_sc[0];
    double L_sum    = g_sc[1];
    double S_fext   = g_sc[2];
    double S_fr     = g_sc[3];
    double S_mrf    = g_sc[4];
    double S_mrp    = g_sc[5];
    double n_fd     = g_sc[6];
    double n_fr     = g_sc[7];
    double n_pin    = g_sc[8];
    float qmax = __uint_as_float(g_qmax_bits);
    float lmax = __uint_as_float(g_lmax_bits);

    double nfd = fmax(n_fd, 1.0);
    double F_char = fmax(sqrt(S_fext / (3.0 * nfd)), 1.0);
    double L_force = S_fr / (F_char * F_char * 3.0 * nfd);

    double q_max = fmax((double)qmax, 1.0);
    double M_char = fmax(q_max * (double)lmax * L_sum / 8.0, 1.0);
    double M2 = M_char * M_char;

    double nfr = fmax(n_fr, 1.0);
    double L_moment = S_mrf / (M2 * 3.0 * nfr);

    double L_neumann = 0.0;
    if (n_pin > 0.0) {
        L_neumann = S_mrp / (M2 * 3.0 * fmax(n_pin, 1.0));
    }

    double L_kin = 0.5 * (sum_rkin / (double)N_ELEMS);

    double total = 1.0 * L_force + 1.0 * L_moment + 1.0 * L_neumann + 0.1 * L_kin;
    out[0] = (float)total;
}

// ---------------- launch ----------------
extern "C" void kernel_launch(void* const* d_in, const int* in_sizes, int n_in,
                              void* d_out, int out_size)
{
    const float* phi   = (const float*)d_in[0];
    const float* gux   = (const float*)d_in[1];
    const float* guz   = (const float*)d_in[2];
    const float* gphi  = (const float*)d_in[3];
    const float* pE    = (const float*)d_in[4];
    const float* pA    = (const float*)d_in[5];
    const float* pI    = (const float*)d_in[6];
    const float* Lq    = (const float*)d_in[7];
    const float* dirs  = (const float*)d_in[8];
    const float* loads = (const float*)d_in[9];
    const float* bcd   = (const float*)d_in[10];
    const float* bcr   = (const float*)d_in[11];
    const int*   conn  = (const int*)d_in[12];
    float* out = (float*)d_out;

    void *pF, *pM, *pX, *pS, *pQ, *pL;
    cudaGetSymbolAddress(&pF, g_F);
    cudaGetSymbolAddress(&pM, g_M);
    cudaGetSymbolAddress(&pX, g_X);
    cudaGetSymbolAddress(&pS, g_sc);
    cudaGetSymbolAddress(&pQ, g_qmax_bits);
    cudaGetSymbolAddress(&pL, g_lmax_bits);

    cudaMemsetAsync(pF, 0, N_NODES * 4 * sizeof(float), 0);
    cudaMemsetAsync(pM, 0, N_NODES * 4 * sizeof(float), 0);
    cudaMemsetAsync(pX, 0, N_NODES * 4 * sizeof(float), 0);
    cudaMemsetAsync(pS, 0, 9 * sizeof(double), 0);
    cudaMemsetAsync(pQ, 0, sizeof(unsigned int), 0);
    cudaMemsetAsync(pL, 0, sizeof(unsigned int), 0);

    detect_conn_kernel<<<1, 32>>>((const unsigned int*)conn);
    elem_kernel<<<2368, 256>>>(phi, gux, guz, gphi, pE, pA, pI, Lq, dirs, loads, conn);
    node_kernel<<<1184, 256>>>(bcd, bcr);
    finalize_kernel<<<1, 1>>>(out);
}